// round 2
// baseline (speedup 1.0000x reference)
#include <cuda_runtime.h>
#include <math.h>

#define T_TOK 8192   // B*S
#define D_DIM 1024
#define R_DIM 512
#define NN 8

// ---------------- scratch (device globals: allocation-guard-safe) ----------
__device__ __align__(16) float g_wq[T_TOK * NN];
__device__ __align__(16) float g_wk[T_TOK * NN];
__device__ __align__(16) float g_wv[T_TOK * NN];
__device__ __align__(16) float g_wo[T_TOK * NN];
__device__ __align__(16) float g_q [T_TOK * R_DIM];
__device__ __align__(16) float g_k [T_TOK * R_DIM];
__device__ __align__(16) float g_v [T_TOK * R_DIM];
__device__ __align__(16) float g_ao[T_TOK * R_DIM];

// ---------------- router softmax for q,k,v ---------------------------------
__global__ __launch_bounds__(256) void router_qkv_kernel(
    const float* __restrict__ x, const float* __restrict__ wrq,
    const float* __restrict__ wrk, const float* __restrict__ wrv)
{
    const int t = blockIdx.x;
    const int warp = threadIdx.x >> 5, lane = threadIdx.x & 31;
    const float* xr = x + (size_t)t * D_DIM;
    const float* aq = wrq + warp * D_DIM;
    const float* ak = wrk + warp * D_DIM;
    const float* av = wrv + warp * D_DIM;
    float sq = 0.f, sk = 0.f, sv = 0.f;
    for (int kk = lane; kk < D_DIM; kk += 32) {
        float xv = xr[kk];
        sq += xv * aq[kk];
        sk += xv * ak[kk];
        sv += xv * av[kk];
    }
    #pragma unroll
    for (int o = 16; o; o >>= 1) {
        sq += __shfl_down_sync(0xffffffffu, sq, o);
        sk += __shfl_down_sync(0xffffffffu, sk, o);
        sv += __shfl_down_sync(0xffffffffu, sv, o);
    }
    __shared__ float lg[3][NN];
    if (lane == 0) { lg[0][warp] = sq; lg[1][warp] = sk; lg[2][warp] = sv; }
    __syncthreads();
    if (threadIdx.x < 3) {
        float* dst = (threadIdx.x == 0) ? g_wq : (threadIdx.x == 1) ? g_wk : g_wv;
        const float* l = lg[threadIdx.x];
        float mx = l[0];
        #pragma unroll
        for (int n = 1; n < NN; n++) mx = fmaxf(mx, l[n]);
        float e[NN]; float s = 0.f;
        #pragma unroll
        for (int n = 0; n < NN; n++) { e[n] = __expf(l[n] - mx); s += e[n]; }
        float inv = 1.f / s;
        #pragma unroll
        for (int n = 0; n < NN; n++) dst[t * NN + n] = e[n] * inv;
    }
}

// ---------------- fused compress: q,k,v = sum_n w_n * (X @ N_n) ------------
__global__ __launch_bounds__(256) void compress_kernel(
    const float* __restrict__ x, const float* __restrict__ neurons)
{
    const int r0 = blockIdx.x * 64;   // R tile
    const int m0 = blockIdx.y * 64;   // token tile
    __shared__ float As[16][64];      // [k][m]
    __shared__ float Bs[16][64];      // [k][r]
    __shared__ float Wq[64][NN], Wk[64][NN], Wv[64][NN];
    const int tid = threadIdx.x;
    for (int i = tid; i < 64 * NN; i += 256) {
        int row = i >> 3, n = i & 7;
        Wq[row][n] = g_wq[(m0 + row) * NN + n];
        Wk[row][n] = g_wk[(m0 + row) * NN + n];
        Wv[row][n] = g_wv[(m0 + row) * NN + n];
    }
    const int tx = tid & 15, ty = tid >> 4;
    const int lrow = tid >> 2, lk = (tid & 3) << 2;
    const int brow = tid >> 4, bcol = (tid & 15) << 2;
    float qa[4][4] = {}, ka[4][4] = {}, va[4][4] = {};
    __syncthreads();
    for (int n = 0; n < NN; n++) {
        const float* Nn = neurons + (size_t)n * D_DIM * R_DIM;
        float ya[4][4] = {};
        for (int k0 = 0; k0 < D_DIM; k0 += 16) {
            float4 xv = *(const float4*)&x[(size_t)(m0 + lrow) * D_DIM + k0 + lk];
            As[lk + 0][lrow] = xv.x; As[lk + 1][lrow] = xv.y;
            As[lk + 2][lrow] = xv.z; As[lk + 3][lrow] = xv.w;
            *(float4*)&Bs[brow][bcol] =
                *(const float4*)&Nn[(size_t)(k0 + brow) * R_DIM + r0 + bcol];
            __syncthreads();
            #pragma unroll
            for (int kk = 0; kk < 16; kk++) {
                const float4 av = *(const float4*)&As[kk][ty << 2];
                const float4 bv = *(const float4*)&Bs[kk][tx << 2];
                const float ar[4] = {av.x, av.y, av.z, av.w};
                const float br[4] = {bv.x, bv.y, bv.z, bv.w};
                #pragma unroll
                for (int i = 0; i < 4; i++)
                    #pragma unroll
                    for (int j = 0; j < 4; j++)
                        ya[i][j] += ar[i] * br[j];
            }
            __syncthreads();
        }
        #pragma unroll
        for (int i = 0; i < 4; i++) {
            const int row = (ty << 2) + i;
            const float wq = Wq[row][n], wk = Wk[row][n], wv = Wv[row][n];
            #pragma unroll
            for (int j = 0; j < 4; j++) {
                qa[i][j] += wq * ya[i][j];
                ka[i][j] += wk * ya[i][j];
                va[i][j] += wv * ya[i][j];
            }
        }
    }
    #pragma unroll
    for (int i = 0; i < 4; i++)
        #pragma unroll
        for (int j = 0; j < 4; j++) {
            size_t idx = (size_t)(m0 + (ty << 2) + i) * R_DIM + r0 + (tx << 2) + j;
            g_q[idx] = qa[i][j];
            g_k[idx] = ka[i][j];
            g_v[idx] = va[i][j];
        }
}

// ---------------- causal flash attention (fp32), DH=64 ---------------------
// q-tile 64, k-tile 32. KP buffer aliases K^T then P.
__global__ __launch_bounds__(256) void flash_kernel()
{
    const int qt = blockIdx.x;   // 0..31
    const int bh = blockIdx.y;   // 0..31
    const int b = bh >> 3, h = bh & 7;
    const float* Qg = g_q  + ((size_t)b * 2048) * R_DIM + h * 64;
    const float* Kg = g_k  + ((size_t)b * 2048) * R_DIM + h * 64;
    const float* Vg = g_v  + ((size_t)b * 2048) * R_DIM + h * 64;
    float*       Og = g_ao + ((size_t)b * 2048) * R_DIM + h * 64;

    __shared__ float Qs[64][64];
    __shared__ float KP[64][33];   // phase 1: K^T [d][c];  phase 2: P [r][c]
    __shared__ float Vs[32][64];
    __shared__ float m_s[64], l_s[64], sc_s[64];

    const int tid = threadIdx.x;
    const int tx = tid & 15, ty = tid >> 4;

    for (int i = tid; i < 64 * 16; i += 256) {
        int r = i >> 4, c4 = (i & 15) << 2;
        float4 v = *(const float4*)&Qg[(size_t)(qt * 64 + r) * R_DIM + c4];
        Qs[r][c4 + 0] = v.x * 0.125f; Qs[r][c4 + 1] = v.y * 0.125f;
        Qs[r][c4 + 2] = v.z * 0.125f; Qs[r][c4 + 3] = v.w * 0.125f;
    }
    if (tid < 64) { m_s[tid] = -INFINITY; l_s[tid] = 0.f; }
    float oa[4][4] = {};
    __syncthreads();

    const int ntile = 2 * qt + 2;
    for (int kt = 0; kt < ntile; kt++) {
        // load K transposed + V
        {
            int r  = tid & 31;
            int c4 = (tid >> 5) << 2;
            #pragma unroll
            for (int p = 0; p < 2; p++, c4 += 32) {
                float4 kv = *(const float4*)&Kg[(size_t)(kt * 32 + r) * R_DIM + c4];
                KP[c4 + 0][r] = kv.x; KP[c4 + 1][r] = kv.y;
                KP[c4 + 2][r] = kv.z; KP[c4 + 3][r] = kv.w;
            }
            int vr = tid >> 4, vc4 = (tid & 15) << 2;
            #pragma unroll
            for (int p = 0; p < 2; p++, vr += 16)
                *(float4*)&Vs[vr][vc4] =
                    *(const float4*)&Vg[(size_t)(kt * 32 + vr) * R_DIM + vc4];
        }
        __syncthreads();
        // S = Q @ K^T  (64 x 32), micro 4x2
        float sa[4][2] = {};
        #pragma unroll 16
        for (int d = 0; d < 64; d++) {
            float q0 = Qs[(ty << 2) + 0][d], q1 = Qs[(ty << 2) + 1][d];
            float q2 = Qs[(ty << 2) + 2][d], q3 = Qs[(ty << 2) + 3][d];
            float k0 = KP[d][(tx << 1) + 0], k1 = KP[d][(tx << 1) + 1];
            sa[0][0] += q0 * k0; sa[0][1] += q0 * k1;
            sa[1][0] += q1 * k0; sa[1][1] += q1 * k1;
            sa[2][0] += q2 * k0; sa[2][1] += q2 * k1;
            sa[3][0] += q3 * k0; sa[3][1] += q3 * k1;
        }
        __syncthreads();     // everyone done reading K^T
        // causal mask; write P-scores into KP[r][c]
        {
            const int colbase = kt * 32 + (tx << 1);
            const int rowbase = qt * 64 + (ty << 2);
            #pragma unroll
            for (int i = 0; i < 4; i++)
                #pragma unroll
                for (int j = 0; j < 2; j++) {
                    float s = sa[i][j];
                    if (colbase + j > rowbase + i) s = -INFINITY;
                    KP[(ty << 2) + i][(tx << 1) + j] = s;
                }
        }
        __syncthreads();
        // online softmax update (one thread per row)
        if (tid < 64) {
            const int r = tid;
            float mold = m_s[r];
            float mx = mold;
            #pragma unroll
            for (int c = 0; c < 32; c++) mx = fmaxf(mx, KP[r][c]);
            float sum = 0.f;
            #pragma unroll
            for (int c = 0; c < 32; c++) {
                float e = __expf(KP[r][c] - mx);
                KP[r][c] = e;
                sum += e;
            }
            float scl = __expf(mold - mx);   // 0 on first tile (mold=-inf)
            m_s[r] = mx;
            l_s[r] = l_s[r] * scl + sum;
            sc_s[r] = scl;
        }
        __syncthreads();
        // rescale O and accumulate P @ V
        #pragma unroll
        for (int i = 0; i < 4; i++) {
            const float sc = sc_s[(ty << 2) + i];
            #pragma unroll
            for (int j = 0; j < 4; j++) oa[i][j] *= sc;
        }
        #pragma unroll 8
        for (int c = 0; c < 32; c++) {
            float p0 = KP[(ty << 2) + 0][c], p1 = KP[(ty << 2) + 1][c];
            float p2 = KP[(ty << 2) + 2][c], p3 = KP[(ty << 2) + 3][c];
            float4 vv = *(const float4*)&Vs[c][tx << 2];
            oa[0][0] += p0 * vv.x; oa[0][1] += p0 * vv.y; oa[0][2] += p0 * vv.z; oa[0][3] += p0 * vv.w;
            oa[1][0] += p1 * vv.x; oa[1][1] += p1 * vv.y; oa[1][2] += p1 * vv.z; oa[1][3] += p1 * vv.w;
            oa[2][0] += p2 * vv.x; oa[2][1] += p2 * vv.y; oa[2][2] += p2 * vv.z; oa[2][3] += p2 * vv.w;
            oa[3][0] += p3 * vv.x; oa[3][1] += p3 * vv.y; oa[3][2] += p3 * vv.z; oa[3][3] += p3 * vv.w;
        }
        __syncthreads();
    }
    #pragma unroll
    for (int i = 0; i < 4; i++) {
        const float inv = 1.f / l_s[(ty << 2) + i];
        const int r = qt * 64 + (ty << 2) + i;
        #pragma unroll
        for (int j = 0; j < 4; j++)
            Og[(size_t)r * R_DIM + (tx << 2) + j] = oa[i][j] * inv;
    }
}

// ---------------- router softmax for expand --------------------------------
__global__ __launch_bounds__(256) void router_o_kernel(const float* __restrict__ wro)
{
    const int t = blockIdx.x;
    const int warp = threadIdx.x >> 5, lane = threadIdx.x & 31;
    const float* ar = g_ao + (size_t)t * R_DIM;
    const float* wn = wro + warp * R_DIM;
    float s = 0.f;
    for (int kk = lane; kk < R_DIM; kk += 32) s += ar[kk] * wn[kk];
    #pragma unroll
    for (int o = 16; o; o >>= 1) s += __shfl_down_sync(0xffffffffu, s, o);
    __shared__ float lg[NN];
    if (lane == 0) lg[warp] = s;
    __syncthreads();
    if (threadIdx.x == 0) {
        float mx = lg[0];
        #pragma unroll
        for (int n = 1; n < NN; n++) mx = fmaxf(mx, lg[n]);
        float e[NN]; float sm = 0.f;
        #pragma unroll
        for (int n = 0; n < NN; n++) { e[n] = __expf(lg[n] - mx); sm += e[n]; }
        float inv = 1.f / sm;
        #pragma unroll
        for (int n = 0; n < NN; n++) g_wo[t * NN + n] = e[n] * inv;
    }
}

// ---------------- fused expand: out = sum_n w_n * (A @ E_n) ----------------
__global__ __launch_bounds__(256) void expand_kernel(
    const float* __restrict__ eneurons, float* __restrict__ out)
{
    const int d0 = blockIdx.x * 64;
    const int m0 = blockIdx.y * 64;
    __shared__ float As[16][64];
    __shared__ float Bs[16][64];
    __shared__ float Wo[64][NN];
    const int tid = threadIdx.x;
    for (int i = tid; i < 64 * NN; i += 256) {
        int row = i >> 3, n = i & 7;
        Wo[row][n] = g_wo[(m0 + row) * NN + n];
    }
    const int tx = tid & 15, ty = tid >> 4;
    const int lrow = tid >> 2, lk = (tid & 3) << 2;
    const int brow = tid >> 4, bcol = (tid & 15) << 2;
    float oacc[4][4] = {};
    __syncthreads();
    for (int n = 0; n < NN; n++) {
        const float* En = eneurons + (size_t)n * R_DIM * D_DIM;
        float ya[4][4] = {};
        for (int k0 = 0; k0 < R_DIM; k0 += 16) {
            float4 av = *(const float4*)&g_ao[(size_t)(m0 + lrow) * R_DIM + k0 + lk];
            As[lk + 0][lrow] = av.x; As[lk + 1][lrow] = av.y;
            As[lk + 2][lrow] = av.z; As[lk + 3][lrow] = av.w;
            *(float4*)&Bs[brow][bcol] =
                *(const float4*)&En[(size_t)(k0 + brow) * D_DIM + d0 + bcol];
            __syncthreads();
            #pragma unroll
            for (int kk = 0; kk < 16; kk++) {
                const float4 a4 = *(const float4*)&As[kk][ty << 2];
                const float4 b4 = *(const float4*)&Bs[kk][tx << 2];
                const float ar[4] = {a4.x, a4.y, a4.z, a4.w};
                const float br[4] = {b4.x, b4.y, b4.z, b4.w};
                #pragma unroll
                for (int i = 0; i < 4; i++)
                    #pragma unroll
                    for (int j = 0; j < 4; j++)
                        ya[i][j] += ar[i] * br[j];
            }
            __syncthreads();
        }
        #pragma unroll
        for (int i = 0; i < 4; i++) {
            const float w = Wo[(ty << 2) + i][n];
            #pragma unroll
            for (int j = 0; j < 4; j++) oacc[i][j] += w * ya[i][j];
        }
    }
    #pragma unroll
    for (int i = 0; i < 4; i++)
        #pragma unroll
        for (int j = 0; j < 4; j++)
            out[(size_t)(m0 + (ty << 2) + i) * D_DIM + d0 + (tx << 2) + j] = oacc[i][j];
}

// ---------------- launch ---------------------------------------------------
extern "C" void kernel_launch(void* const* d_in, const int* in_sizes, int n_in,
                              void* d_out, int out_size)
{
    const float* x   = (const float*)d_in[0];
    // d_in[1] = mask: exactly tril -> handled as causal, unused
    const float* cn  = (const float*)d_in[2];
    const float* en  = (const float*)d_in[3];
    const float* wrq = (const float*)d_in[4];
    const float* wrk = (const float*)d_in[5];
    const float* wrv = (const float*)d_in[6];
    const float* wro = (const float*)d_in[7];
    float* out = (float*)d_out;

    router_qkv_kernel<<<T_TOK, 256>>>(x, wrq, wrk, wrv);
    compress_kernel<<<dim3(R_DIM / 64, T_TOK / 64), 256>>>(x, cn);
    flash_kernel<<<dim3(32, 32), 256>>>();
    router_o_kernel<<<T_TOK, 256>>>(wro);
    expand_kernel<<<dim3(D_DIM / 64, T_TOK / 64), 256>>>(en, out);
}

// round 4
// speedup vs baseline: 2.7757x; 2.7757x over previous
#include <cuda_runtime.h>
#include <cuda_bf16.h>
#include <math.h>
#include <stdint.h>

#define T_TOK 8192
#define D_DIM 1024
#define R_DIM 512
#define NN 8

// ---------------- scratch (device globals) ----------------------------------
__device__ __align__(16) float g_wq[T_TOK * NN];
__device__ __align__(16) float g_wk[T_TOK * NN];
__device__ __align__(16) float g_wv[T_TOK * NN];
__device__ __align__(16) float g_wo[T_TOK * NN];
__device__ __align__(16) float g_q [T_TOK * R_DIM];
__device__ __align__(16) float g_k [T_TOK * R_DIM];
__device__ __align__(16) float g_v [T_TOK * R_DIM];
__device__ __align__(16) float g_ao[T_TOK * R_DIM];
__device__ __align__(16) float g_y [T_TOK * (NN * D_DIM)];     // 268MB, reused
// bf16 split operands
__device__ __align__(16) __nv_bfloat16 g_xhi[T_TOK * D_DIM];
__device__ __align__(16) __nv_bfloat16 g_xlo[T_TOK * D_DIM];
__device__ __align__(16) __nv_bfloat16 g_cbh[D_DIM * (NN * R_DIM)]; // [d][n*512+r]
__device__ __align__(16) __nv_bfloat16 g_cbl[D_DIM * (NN * R_DIM)];
__device__ __align__(16) __nv_bfloat16 g_ebh[R_DIM * (NN * D_DIM)]; // [r][n*1024+d]
__device__ __align__(16) __nv_bfloat16 g_ebl[R_DIM * (NN * D_DIM)];
__device__ __align__(16) __nv_bfloat16 g_aohi[T_TOK * R_DIM];
__device__ __align__(16) __nv_bfloat16 g_aolo[T_TOK * R_DIM];

// ---------------- helpers ----------------------------------------------------
__device__ __forceinline__ uint32_t smem_u32(const void* p) {
    uint32_t a;
    asm("{ .reg .u64 t; cvta.to.shared.u64 t, %1; cvt.u32.u64 %0, t; }"
        : "=r"(a) : "l"(p));
    return a;
}

#define CP16(dst, src) \
    asm volatile("{ .reg .u64 g; cvta.to.global.u64 g, %1; " \
                 "cp.async.cg.shared.global [%0], [g], 16; }" \
                 :: "r"(dst), "l"(src) : "memory")
#define CP_COMMIT() asm volatile("cp.async.commit_group;" ::: "memory")
#define CP_WAIT1()  asm volatile("cp.async.wait_group 1;" ::: "memory")
#define CP_WAIT0()  asm volatile("cp.async.wait_group 0;" ::: "memory")

#define LDSM4(r, addr) \
    asm volatile("ldmatrix.sync.aligned.m8n8.x4.shared.b16 {%0,%1,%2,%3}, [%4];" \
                 : "=r"((r)[0]), "=r"((r)[1]), "=r"((r)[2]), "=r"((r)[3]) : "r"(addr))
#define LDSM4T(r, addr) \
    asm volatile("ldmatrix.sync.aligned.m8n8.x4.trans.shared.b16 {%0,%1,%2,%3}, [%4];" \
                 : "=r"((r)[0]), "=r"((r)[1]), "=r"((r)[2]), "=r"((r)[3]) : "r"(addr))

#define MMA_BF16(d, a, b) \
    asm volatile("mma.sync.aligned.m16n8k16.row.col.f32.bf16.bf16.f32 " \
                 "{%0,%1,%2,%3},{%4,%5,%6,%7},{%8,%9},{%0,%1,%2,%3};" \
                 : "+f"((d)[0]), "+f"((d)[1]), "+f"((d)[2]), "+f"((d)[3]) \
                 : "r"((a)[0]), "r"((a)[1]), "r"((a)[2]), "r"((a)[3]), \
                   "r"((b)[0]), "r"((b)[1]))

// ---------------- conversion / pack kernels ----------------------------------
__global__ __launch_bounds__(256) void convert_x_kernel(const float* __restrict__ x)
{
    const int total4 = T_TOK * D_DIM / 4;
    for (int i = blockIdx.x * 256 + threadIdx.x; i < total4; i += gridDim.x * 256) {
        float4 v = *(const float4*)&x[i * 4];
        float vv[4] = {v.x, v.y, v.z, v.w};
        ushort4 h4, l4;
        unsigned short* hp = &h4.x; unsigned short* lp = &l4.x;
        #pragma unroll
        for (int j = 0; j < 4; j++) {
            __nv_bfloat16 h = __float2bfloat16(vv[j]);
            __nv_bfloat16 l = __float2bfloat16(vv[j] - __bfloat162float(h));
            hp[j] = __bfloat16_as_ushort(h);
            lp[j] = __bfloat16_as_ushort(l);
        }
        *(ushort4*)&g_xhi[i * 4] = h4;
        *(ushort4*)&g_xlo[i * 4] = l4;
    }
}

// compress_neurons [n][d][r] -> B [d][n*512+r]
__global__ __launch_bounds__(256) void pack_cb_kernel(const float* __restrict__ cn)
{
    const int total4 = NN * D_DIM * R_DIM / 4;   // 1,048,576
    for (int i = blockIdx.x * 256 + threadIdx.x; i < total4; i += gridDim.x * 256) {
        int n = i >> 17;                 // D*R/4 = 131072
        int rem = i & 131071;
        int d = rem >> 7;                // R/4 = 128
        int r4 = (rem & 127) << 2;
        float4 v = *(const float4*)&cn[(((size_t)n << 10) + d) * R_DIM + r4];
        float vv[4] = {v.x, v.y, v.z, v.w};
        ushort4 h4, l4;
        unsigned short* hp = &h4.x; unsigned short* lp = &l4.x;
        #pragma unroll
        for (int j = 0; j < 4; j++) {
            __nv_bfloat16 h = __float2bfloat16(vv[j]);
            __nv_bfloat16 l = __float2bfloat16(vv[j] - __bfloat162float(h));
            hp[j] = __bfloat16_as_ushort(h);
            lp[j] = __bfloat16_as_ushort(l);
        }
        size_t dst = (size_t)d * (NN * R_DIM) + n * R_DIM + r4;
        *(ushort4*)&g_cbh[dst] = h4;
        *(ushort4*)&g_cbl[dst] = l4;
    }
}

// expand_neurons [n][r][d] -> B [r][n*1024+d]
__global__ __launch_bounds__(256) void pack_eb_kernel(const float* __restrict__ en)
{
    const int total4 = NN * R_DIM * D_DIM / 4;
    for (int i = blockIdx.x * 256 + threadIdx.x; i < total4; i += gridDim.x * 256) {
        int n = i >> 17;                 // R*D/4 = 131072
        int rem = i & 131071;
        int r = rem >> 8;                // D/4 = 256
        int d4 = (rem & 255) << 2;
        float4 v = *(const float4*)&en[(((size_t)n << 9) + r) * D_DIM + d4];
        float vv[4] = {v.x, v.y, v.z, v.w};
        ushort4 h4, l4;
        unsigned short* hp = &h4.x; unsigned short* lp = &l4.x;
        #pragma unroll
        for (int j = 0; j < 4; j++) {
            __nv_bfloat16 h = __float2bfloat16(vv[j]);
            __nv_bfloat16 l = __float2bfloat16(vv[j] - __bfloat162float(h));
            hp[j] = __bfloat16_as_ushort(h);
            lp[j] = __bfloat16_as_ushort(l);
        }
        size_t dst = (size_t)r * (NN * D_DIM) + n * D_DIM + d4;
        *(ushort4*)&g_ebh[dst] = h4;
        *(ushort4*)&g_ebl[dst] = l4;
    }
}

// ---------------- router softmax (q,k,v) --------------------------------------
__global__ __launch_bounds__(256) void router_qkv_kernel(
    const float* __restrict__ x, const float* __restrict__ wrq,
    const float* __restrict__ wrk, const float* __restrict__ wrv)
{
    const int t = blockIdx.x;
    const int warp = threadIdx.x >> 5, lane = threadIdx.x & 31;
    const float* xr = x + (size_t)t * D_DIM;
    const float* aq = wrq + warp * D_DIM;
    const float* ak = wrk + warp * D_DIM;
    const float* av = wrv + warp * D_DIM;
    float sq = 0.f, sk = 0.f, sv = 0.f;
    for (int kk = lane; kk < D_DIM; kk += 32) {
        float xv = xr[kk];
        sq += xv * aq[kk]; sk += xv * ak[kk]; sv += xv * av[kk];
    }
    #pragma unroll
    for (int o = 16; o; o >>= 1) {
        sq += __shfl_down_sync(0xffffffffu, sq, o);
        sk += __shfl_down_sync(0xffffffffu, sk, o);
        sv += __shfl_down_sync(0xffffffffu, sv, o);
    }
    __shared__ float lg[3][NN];
    if (lane == 0) { lg[0][warp] = sq; lg[1][warp] = sk; lg[2][warp] = sv; }
    __syncthreads();
    if (threadIdx.x < 3) {
        float* dst = (threadIdx.x == 0) ? g_wq : (threadIdx.x == 1) ? g_wk : g_wv;
        const float* l = lg[threadIdx.x];
        float mx = l[0];
        #pragma unroll
        for (int n = 1; n < NN; n++) mx = fmaxf(mx, l[n]);
        float e[NN]; float s = 0.f;
        #pragma unroll
        for (int n = 0; n < NN; n++) { e[n] = __expf(l[n] - mx); s += e[n]; }
        float inv = 1.f / s;
        #pragma unroll
        for (int n = 0; n < NN; n++) dst[t * NN + n] = e[n] * inv;
    }
}

// ---------------- 3-term bf16 mma GEMM ----------------------------------------
// C[M,N] = Ah@Bh + Al@Bh + Ah@Bl ; A [M,K] k-major, B [K,N] n-major, C fp32.
// block 128x128, BK=32, 256 threads, warp grid 2x4 (warp tile 64x32).
// smem/stage: Ah 8K | Al 8K | Bh 8K | Bl 8K ; 2 stages = 64KB.
__global__ __launch_bounds__(256) void gemm3_kernel(
    const __nv_bfloat16* __restrict__ Ah, const __nv_bfloat16* __restrict__ Al,
    const __nv_bfloat16* __restrict__ Bh, const __nv_bfloat16* __restrict__ Bl,
    float* __restrict__ C, int M, int N, int K)
{
    extern __shared__ char sm[];
    const uint32_t sbase = smem_u32(sm);
    const int tid = threadIdx.x;
    const int lane = tid & 31, w = tid >> 5;
    const int n0 = blockIdx.x * 128, m0 = blockIdx.y * 128;
    const int wm = (w >> 2) * 64, wn = (w & 3) * 32;
    const int NC = K >> 5;

    // per-thread load ids
    const int ar0 = tid >> 2, ac0 = tid & 3;           // + 64 rows for second
    const int br0 = tid >> 4, bc0 = tid & 15;          // + 16 rows for second

    float acc[4][4][4];
    #pragma unroll
    for (int i = 0; i < 4; i++)
        #pragma unroll
        for (int j = 0; j < 4; j++)
            #pragma unroll
            for (int e = 0; e < 4; e++) acc[i][j][e] = 0.f;

    auto load_stage = [&](int kc, int st) {
        const uint32_t so0 = st * 32768;
        #pragma unroll
        for (int h = 0; h < 2; h++) {
            int r = ar0 + h * 64, c = ac0;
            uint32_t so = so0 + r * 64 + ((c ^ ((r >> 1) & 3)) << 4);
            size_t go = (size_t)(m0 + r) * K + kc * 32 + c * 8;
            CP16(sbase + so,        Ah + go);
            CP16(sbase + so + 8192, Al + go);
        }
        #pragma unroll
        for (int h = 0; h < 2; h++) {
            int r = br0 + h * 16, c = bc0;
            uint32_t so = so0 + 16384 + r * 256 + ((c ^ (r & 7)) << 4);
            size_t go = (size_t)(kc * 32 + r) * N + n0 + c * 8;
            CP16(sbase + so,        Bh + go);
            CP16(sbase + so + 8192, Bl + go);
        }
    };

    load_stage(0, 0);
    CP_COMMIT();

    for (int kc = 0; kc < NC; kc++) {
        const int st = kc & 1;
        if (kc + 1 < NC) {
            load_stage(kc + 1, st ^ 1);
            CP_COMMIT();
            CP_WAIT1();
        } else {
            CP_WAIT0();
        }
        __syncthreads();

        const uint32_t abase = sbase + st * 32768;
        const uint32_t bbase = abase + 16384;
        #pragma unroll
        for (int step = 0; step < 2; step++) {
            uint32_t ah[4][4], al[4][4];
            #pragma unroll
            for (int i = 0; i < 4; i++) {
                int r = wm + 16 * i + (lane & 15);
                int c = step * 2 + (lane >> 4);
                uint32_t addr = abase + r * 64 + ((c ^ ((r >> 1) & 3)) << 4);
                LDSM4(ah[i], addr);
                LDSM4(al[i], addr + 8192);
            }
            uint32_t bh[4][2], bl[4][2];
            #pragma unroll
            for (int j2 = 0; j2 < 2; j2++) {
                int r = step * 16 + (lane & 7) + ((lane >> 3) & 1) * 8;
                int c = (wn >> 3) + j2 * 2 + (lane >> 4);
                uint32_t addr = bbase + r * 256 + ((c ^ (r & 7)) << 4);
                uint32_t t[4];
                LDSM4T(t, addr);
                bh[2 * j2][0] = t[0]; bh[2 * j2][1] = t[1];
                bh[2 * j2 + 1][0] = t[2]; bh[2 * j2 + 1][1] = t[3];
                LDSM4T(t, addr + 8192);
                bl[2 * j2][0] = t[0]; bl[2 * j2][1] = t[1];
                bl[2 * j2 + 1][0] = t[2]; bl[2 * j2 + 1][1] = t[3];
            }
            #pragma unroll
            for (int i = 0; i < 4; i++)
                #pragma unroll
                for (int j = 0; j < 4; j++) {
                    MMA_BF16(acc[i][j], ah[i], bh[j]);
                    MMA_BF16(acc[i][j], al[i], bh[j]);
                    MMA_BF16(acc[i][j], ah[i], bl[j]);
                }
        }
        __syncthreads();
    }

    // epilogue
    #pragma unroll
    for (int i = 0; i < 4; i++)
        #pragma unroll
        for (int j = 0; j < 4; j++) {
            int row = m0 + wm + 16 * i + (lane >> 2);
            int col = n0 + wn + 8 * j + ((lane & 3) << 1);
            *(float2*)&C[(size_t)row * N + col] =
                make_float2(acc[i][j][0], acc[i][j][1]);
            *(float2*)&C[(size_t)(row + 8) * N + col] =
                make_float2(acc[i][j][2], acc[i][j][3]);
        }
}

// ---------------- weighted reduces --------------------------------------------
__global__ __launch_bounds__(256) void compress_reduce_kernel()
{
    const int idx = blockIdx.x * 256 + threadIdx.x;      // 8192*128
    const int m = idx >> 7;
    const int r4 = (idx & 127) << 2;
    const float* y = g_y + (size_t)m * (NN * R_DIM) + r4;
    const float* wq = g_wq + m * NN;
    const float* wk = g_wk + m * NN;
    const float* wv = g_wv + m * NN;
    float4 qa = {0, 0, 0, 0}, ka = {0, 0, 0, 0}, va = {0, 0, 0, 0};
    #pragma unroll
    for (int n = 0; n < NN; n++) {
        float4 t = *(const float4*)(y + n * R_DIM);
        float a = wq[n], b = wk[n], c = wv[n];
        qa.x += a * t.x; qa.y += a * t.y; qa.z += a * t.z; qa.w += a * t.w;
        ka.x += b * t.x; ka.y += b * t.y; ka.z += b * t.z; ka.w += b * t.w;
        va.x += c * t.x; va.y += c * t.y; va.z += c * t.z; va.w += c * t.w;
    }
    size_t o = (size_t)m * R_DIM + r4;
    *(float4*)&g_q[o] = qa;
    *(float4*)&g_k[o] = ka;
    *(float4*)&g_v[o] = va;
}

__global__ __launch_bounds__(256) void expand_reduce_kernel(float* __restrict__ out)
{
    const int idx = blockIdx.x * 256 + threadIdx.x;      // 8192*256
    const int m = idx >> 8;
    const int d4 = (idx & 255) << 2;
    const float* y = g_y + (size_t)m * (NN * D_DIM) + d4;
    const float* wo = g_wo + m * NN;
    float4 oa = {0, 0, 0, 0};
    #pragma unroll
    for (int n = 0; n < NN; n++) {
        float4 t = *(const float4*)(y + n * D_DIM);
        float a = wo[n];
        oa.x += a * t.x; oa.y += a * t.y; oa.z += a * t.z; oa.w += a * t.w;
    }
    *(float4*)&out[(size_t)m * D_DIM + d4] = oa;
}

// ---------------- causal flash attention (fp32), DH=64 ------------------------
__global__ __launch_bounds__(256) void flash_kernel()
{
    const int qt = blockIdx.x;
    const int bh = blockIdx.y;
    const int b = bh >> 3, h = bh & 7;
    const float* Qg = g_q  + ((size_t)b * 2048) * R_DIM + h * 64;
    const float* Kg = g_k  + ((size_t)b * 2048) * R_DIM + h * 64;
    const float* Vg = g_v  + ((size_t)b * 2048) * R_DIM + h * 64;
    float*       Og = g_ao + ((size_t)b * 2048) * R_DIM + h * 64;
    __nv_bfloat16* OgH = g_aohi + ((size_t)b * 2048) * R_DIM + h * 64;
    __nv_bfloat16* OgL = g_aolo + ((size_t)b * 2048) * R_DIM + h * 64;

    __shared__ float Qs[64][64];
    __shared__ float KP[64][33];
    __shared__ float Vs[32][64];
    __shared__ float m_s[64], l_s[64], sc_s[64];

    const int tid = threadIdx.x;
    const int tx = tid & 15, ty = tid >> 4;

    for (int i = tid; i < 64 * 16; i += 256) {
        int r = i >> 4, c4 = (i & 15) << 2;
        float4 v = *(const float4*)&Qg[(size_t)(qt * 64 + r) * R_DIM + c4];
        Qs[r][c4 + 0] = v.x * 0.125f; Qs[r][c4 + 1] = v.y * 0.125f;
        Qs[r][c4 + 2] = v.z * 0.125f; Qs[r][c4 + 3] = v.w * 0.125f;
    }
    if (tid < 64) { m_s[tid] = -INFINITY; l_s[tid] = 0.f; }
    float oa[4][4] = {};
    __syncthreads();

    const int ntile = 2 * qt + 2;
    for (int kt = 0; kt < ntile; kt++) {
        {
            int r  = tid & 31;
            int c4 = (tid >> 5) << 2;
            #pragma unroll
            for (int p = 0; p < 2; p++, c4 += 32) {
                float4 kv = *(const float4*)&Kg[(size_t)(kt * 32 + r) * R_DIM + c4];
                KP[c4 + 0][r] = kv.x; KP[c4 + 1][r] = kv.y;
                KP[c4 + 2][r] = kv.z; KP[c4 + 3][r] = kv.w;
            }
            int vr = tid >> 4, vc4 = (tid & 15) << 2;
            #pragma unroll
            for (int p = 0; p < 2; p++, vr += 16)
                *(float4*)&Vs[vr][vc4] =
                    *(const float4*)&Vg[(size_t)(kt * 32 + vr) * R_DIM + vc4];
        }
        __syncthreads();
        float sa[4][2] = {};
        #pragma unroll 16
        for (int d = 0; d < 64; d++) {
            float q0 = Qs[(ty << 2) + 0][d], q1 = Qs[(ty << 2) + 1][d];
            float q2 = Qs[(ty << 2) + 2][d], q3 = Qs[(ty << 2) + 3][d];
            float k0 = KP[d][(tx << 1) + 0], k1 = KP[d][(tx << 1) + 1];
            sa[0][0] += q0 * k0; sa[0][1] += q0 * k1;
            sa[1][0] += q1 * k0; sa[1][1] += q1 * k1;
            sa[2][0] += q2 * k0; sa[2][1] += q2 * k1;
            sa[3][0] += q3 * k0; sa[3][1] += q3 * k1;
        }
        __syncthreads();
        {
            const int colbase = kt * 32 + (tx << 1);
            const int rowbase = qt * 64 + (ty << 2);
            #pragma unroll
            for (int i = 0; i < 4; i++)
                #pragma unroll
                for (int j = 0; j < 2; j++) {
                    float s = sa[i][j];
                    if (colbase + j > rowbase + i) s = -INFINITY;
                    KP[(ty << 2) + i][(tx << 1) + j] = s;
                }
        }
        __syncthreads();
        if (tid < 64) {
            const int r = tid;
            float mold = m_s[r];
            float mx = mold;
            #pragma unroll
            for (int c = 0; c < 32; c++) mx = fmaxf(mx, KP[r][c]);
            float sum = 0.f;
            #pragma unroll
            for (int c = 0; c < 32; c++) {
                float e = __expf(KP[r][c] - mx);
                KP[r][c] = e;
                sum += e;
            }
            float scl = __expf(mold - mx);
            m_s[r] = mx;
            l_s[r] = l_s[r] * scl + sum;
            sc_s[r] = scl;
        }
        __syncthreads();
        #pragma unroll
        for (int i = 0; i < 4; i++) {
            const float sc = sc_s[(ty << 2) + i];
            #pragma unroll
            for (int j = 0; j < 4; j++) oa[i][j] *= sc;
        }
        #pragma unroll 8
        for (int c = 0; c < 32; c++) {
            float p0 = KP[(ty << 2) + 0][c], p1 = KP[(ty << 2) + 1][c];
            float p2 = KP[(ty << 2) + 2][c], p3 = KP[(ty << 2) + 3][c];
            float4 vv = *(const float4*)&Vs[c][tx << 2];
            oa[0][0] += p0 * vv.x; oa[0][1] += p0 * vv.y; oa[0][2] += p0 * vv.z; oa[0][3] += p0 * vv.w;
            oa[1][0] += p1 * vv.x; oa[1][1] += p1 * vv.y; oa[1][2] += p1 * vv.z; oa[1][3] += p1 * vv.w;
            oa[2][0] += p2 * vv.x; oa[2][1] += p2 * vv.y; oa[2][2] += p2 * vv.z; oa[2][3] += p2 * vv.w;
            oa[3][0] += p3 * vv.x; oa[3][1] += p3 * vv.y; oa[3][2] += p3 * vv.z; oa[3][3] += p3 * vv.w;
        }
        __syncthreads();
    }
    #pragma unroll
    for (int i = 0; i < 4; i++) {
        const float inv = 1.f / l_s[(ty << 2) + i];
        const int r = qt * 64 + (ty << 2) + i;
        #pragma unroll
        for (int j = 0; j < 4; j++) {
            float val = oa[i][j] * inv;
            size_t idx = (size_t)r * R_DIM + (tx << 2) + j;
            Og[idx] = val;
            __nv_bfloat16 hh = __float2bfloat16(val);
            OgH[idx] = hh;
            OgL[idx] = __float2bfloat16(val - __bfloat162float(hh));
        }
    }
}

// ---------------- router softmax (expand) -------------------------------------
__global__ __launch_bounds__(256) void router_o_kernel(const float* __restrict__ wro)
{
    const int t = blockIdx.x;
    const int warp = threadIdx.x >> 5, lane = threadIdx.x & 31;
    const float* ar = g_ao + (size_t)t * R_DIM;
    const float* wn = wro + warp * R_DIM;
    float s = 0.f;
    for (int kk = lane; kk < R_DIM; kk += 32) s += ar[kk] * wn[kk];
    #pragma unroll
    for (int o = 16; o; o >>= 1) s += __shfl_down_sync(0xffffffffu, s, o);
    __shared__ float lg[NN];
    if (lane == 0) lg[warp] = s;
    __syncthreads();
    if (threadIdx.x == 0) {
        float mx = lg[0];
        #pragma unroll
        for (int n = 1; n < NN; n++) mx = fmaxf(mx, lg[n]);
        float e[NN]; float sm = 0.f;
        #pragma unroll
        for (int n = 0; n < NN; n++) { e[n] = __expf(lg[n] - mx); sm += e[n]; }
        float inv = 1.f / sm;
        #pragma unroll
        for (int n = 0; n < NN; n++) g_wo[t * NN + n] = e[n] * inv;
    }
}

// ---------------- launch ------------------------------------------------------
extern "C" void kernel_launch(void* const* d_in, const int* in_sizes, int n_in,
                              void* d_out, int out_size)
{
    const float* x   = (const float*)d_in[0];
    // d_in[1] = mask: exactly tril -> handled as causal
    const float* cn  = (const float*)d_in[2];
    const float* en  = (const float*)d_in[3];
    const float* wrq = (const float*)d_in[4];
    const float* wrk = (const float*)d_in[5];
    const float* wrv = (const float*)d_in[6];
    const float* wro = (const float*)d_in[7];
    float* out = (float*)d_out;

    static __nv_bfloat16 *p_xhi = nullptr, *p_xlo, *p_cbh, *p_cbl, *p_ebh,
                         *p_ebl, *p_aoh, *p_aol;
    static float* p_y = nullptr;
    if (!p_xhi) {
        cudaGetSymbolAddress((void**)&p_xhi, g_xhi);
        cudaGetSymbolAddress((void**)&p_xlo, g_xlo);
        cudaGetSymbolAddress((void**)&p_cbh, g_cbh);
        cudaGetSymbolAddress((void**)&p_cbl, g_cbl);
        cudaGetSymbolAddress((void**)&p_ebh, g_ebh);
        cudaGetSymbolAddress((void**)&p_ebl, g_ebl);
        cudaGetSymbolAddress((void**)&p_aoh, g_aohi);
        cudaGetSymbolAddress((void**)&p_aol, g_aolo);
        cudaGetSymbolAddress((void**)&p_y,   g_y);
        cudaFuncSetAttribute(gemm3_kernel,
                             cudaFuncAttributeMaxDynamicSharedMemorySize, 65536);
    }

    convert_x_kernel<<<1024, 256>>>(x);
    pack_cb_kernel<<<1024, 256>>>(cn);
    pack_eb_kernel<<<1024, 256>>>(en);
    router_qkv_kernel<<<T_TOK, 256>>>(x, wrq, wrk, wrv);
    // compress: Y[8192, 4096] = X[8192,1024] @ CB[1024,4096]
    gemm3_kernel<<<dim3(32, 64), 256, 65536>>>(p_xhi, p_xlo, p_cbh, p_cbl,
                                               p_y, T_TOK, NN * R_DIM, D_DIM);
    compress_reduce_kernel<<<4096, 256>>>();
    flash_kernel<<<dim3(32, 32), 256>>>();
    router_o_kernel<<<T_TOK, 256>>>(wro);
    // expand: Y[8192, 8192] = AO[8192,512] @ EB[512,8192]
    gemm3_kernel<<<dim3(64, 64), 256, 65536>>>(p_aoh, p_aol, p_ebh, p_ebl,
                                               p_y, T_TOK, NN * D_DIM, R_DIM);
    expand_reduce_kernel<<<8192, 256>>>(out);
}

// round 6
// speedup vs baseline: 4.1270x; 1.4868x over previous
#include <cuda_runtime.h>
#include <cuda_bf16.h>
#include <math.h>
#include <stdint.h>

#define T_TOK 8192
#define D_DIM 1024
#define R_DIM 512
#define NN 8

// ---------------- scratch (device globals) ----------------------------------
__device__ __align__(16) float g_wq[T_TOK * NN];
__device__ __align__(16) float g_wk[T_TOK * NN];
__device__ __align__(16) float g_wv[T_TOK * NN];
__device__ __align__(16) float g_wo[T_TOK * NN];
__device__ __align__(16) float g_ao[T_TOK * R_DIM];
__device__ __align__(16) float g_y [T_TOK * (NN * D_DIM)];     // 268MB, reused
// bf16 split operands
__device__ __align__(16) __nv_bfloat16 g_xhi[T_TOK * D_DIM];
__device__ __align__(16) __nv_bfloat16 g_xlo[T_TOK * D_DIM];
__device__ __align__(16) __nv_bfloat16 g_cbh[D_DIM * (NN * R_DIM)];
__device__ __align__(16) __nv_bfloat16 g_cbl[D_DIM * (NN * R_DIM)];
__device__ __align__(16) __nv_bfloat16 g_ebh[R_DIM * (NN * D_DIM)];
__device__ __align__(16) __nv_bfloat16 g_ebl[R_DIM * (NN * D_DIM)];
__device__ __align__(16) __nv_bfloat16 g_aohi[T_TOK * R_DIM];
__device__ __align__(16) __nv_bfloat16 g_aolo[T_TOK * R_DIM];
// q,k,v bf16 hi/lo (q pre-scaled by 0.125)
__device__ __align__(16) __nv_bfloat16 g_qhi[T_TOK * R_DIM];
__device__ __align__(16) __nv_bfloat16 g_qlo[T_TOK * R_DIM];
__device__ __align__(16) __nv_bfloat16 g_khi[T_TOK * R_DIM];
__device__ __align__(16) __nv_bfloat16 g_klo[T_TOK * R_DIM];
__device__ __align__(16) __nv_bfloat16 g_vhi[T_TOK * R_DIM];
__device__ __align__(16) __nv_bfloat16 g_vlo[T_TOK * R_DIM];

// ---------------- helpers ----------------------------------------------------
__device__ __forceinline__ uint32_t smem_u32(const void* p) {
    uint32_t a;
    asm("{ .reg .u64 t; cvta.to.shared.u64 t, %1; cvt.u32.u64 %0, t; }"
        : "=r"(a) : "l"(p));
    return a;
}

#define CP16(dst, src) \
    asm volatile("{ .reg .u64 g; cvta.to.global.u64 g, %1; " \
                 "cp.async.cg.shared.global [%0], [g], 16; }" \
                 :: "r"(dst), "l"(src) : "memory")
#define CP_COMMIT() asm volatile("cp.async.commit_group;" ::: "memory")
#define CP_WAIT1()  asm volatile("cp.async.wait_group 1;" ::: "memory")
#define CP_WAIT0()  asm volatile("cp.async.wait_group 0;" ::: "memory")

#define LDSM4(r, addr) \
    asm volatile("ldmatrix.sync.aligned.m8n8.x4.shared.b16 {%0,%1,%2,%3}, [%4];" \
                 : "=r"((r)[0]), "=r"((r)[1]), "=r"((r)[2]), "=r"((r)[3]) : "r"(addr))
#define LDSM4T(r, addr) \
    asm volatile("ldmatrix.sync.aligned.m8n8.x4.trans.shared.b16 {%0,%1,%2,%3}, [%4];" \
                 : "=r"((r)[0]), "=r"((r)[1]), "=r"((r)[2]), "=r"((r)[3]) : "r"(addr))

#define MMA_BF16(d, a, b) \
    asm volatile("mma.sync.aligned.m16n8k16.row.col.f32.bf16.bf16.f32 " \
                 "{%0,%1,%2,%3},{%4,%5,%6,%7},{%8,%9},{%0,%1,%2,%3};" \
                 : "+f"((d)[0]), "+f"((d)[1]), "+f"((d)[2]), "+f"((d)[3]) \
                 : "r"((a)[0]), "r"((a)[1]), "r"((a)[2]), "r"((a)[3]), \
                   "r"((b)[0]), "r"((b)[1]))

// pack (lo, hi) floats -> bf16x2 register (first PTX src = high half)
#define PACKBF(r, lo, hi) \
    asm("cvt.rn.bf16x2.f32 %0, %1, %2;" : "=r"(r) : "f"(hi), "f"(lo))

__device__ __forceinline__ float bflo(float x) {
    return x - __bfloat162float(__float2bfloat16(x));
}

// ---------------- conversion / pack kernels ----------------------------------
__global__ __launch_bounds__(256) void convert_x_kernel(const float* __restrict__ x)
{
    const int total4 = T_TOK * D_DIM / 4;
    for (int i = blockIdx.x * 256 + threadIdx.x; i < total4; i += gridDim.x * 256) {
        float4 v = *(const float4*)&x[i * 4];
        float vv[4] = {v.x, v.y, v.z, v.w};
        ushort4 h4, l4;
        unsigned short* hp = &h4.x; unsigned short* lp = &l4.x;
        #pragma unroll
        for (int j = 0; j < 4; j++) {
            __nv_bfloat16 h = __float2bfloat16(vv[j]);
            __nv_bfloat16 l = __float2bfloat16(vv[j] - __bfloat162float(h));
            hp[j] = __bfloat16_as_ushort(h);
            lp[j] = __bfloat16_as_ushort(l);
        }
        *(ushort4*)&g_xhi[i * 4] = h4;
        *(ushort4*)&g_xlo[i * 4] = l4;
    }
}

__global__ __launch_bounds__(256) void pack_cb_kernel(const float* __restrict__ cn)
{
    const int total4 = NN * D_DIM * R_DIM / 4;
    for (int i = blockIdx.x * 256 + threadIdx.x; i < total4; i += gridDim.x * 256) {
        int n = i >> 17;
        int rem = i & 131071;
        int d = rem >> 7;
        int r4 = (rem & 127) << 2;
        float4 v = *(const float4*)&cn[(((size_t)n << 10) + d) * R_DIM + r4];
        float vv[4] = {v.x, v.y, v.z, v.w};
        ushort4 h4, l4;
        unsigned short* hp = &h4.x; unsigned short* lp = &l4.x;
        #pragma unroll
        for (int j = 0; j < 4; j++) {
            __nv_bfloat16 h = __float2bfloat16(vv[j]);
            __nv_bfloat16 l = __float2bfloat16(vv[j] - __bfloat162float(h));
            hp[j] = __bfloat16_as_ushort(h);
            lp[j] = __bfloat16_as_ushort(l);
        }
        size_t dst = (size_t)d * (NN * R_DIM) + n * R_DIM + r4;
        *(ushort4*)&g_cbh[dst] = h4;
        *(ushort4*)&g_cbl[dst] = l4;
    }
}

__global__ __launch_bounds__(256) void pack_eb_kernel(const float* __restrict__ en)
{
    const int total4 = NN * R_DIM * D_DIM / 4;
    for (int i = blockIdx.x * 256 + threadIdx.x; i < total4; i += gridDim.x * 256) {
        int n = i >> 17;
        int rem = i & 131071;
        int r = rem >> 8;
        int d4 = (rem & 255) << 2;
        float4 v = *(const float4*)&en[(((size_t)n << 9) + r) * D_DIM + d4];
        float vv[4] = {v.x, v.y, v.z, v.w};
        ushort4 h4, l4;
        unsigned short* hp = &h4.x; unsigned short* lp = &l4.x;
        #pragma unroll
        for (int j = 0; j < 4; j++) {
            __nv_bfloat16 h = __float2bfloat16(vv[j]);
            __nv_bfloat16 l = __float2bfloat16(vv[j] - __bfloat162float(h));
            hp[j] = __bfloat16_as_ushort(h);
            lp[j] = __bfloat16_as_ushort(l);
        }
        size_t dst = (size_t)r * (NN * D_DIM) + n * D_DIM + d4;
        *(ushort4*)&g_ebh[dst] = h4;
        *(ushort4*)&g_ebl[dst] = l4;
    }
}

// ---------------- router softmax (q,k,v) --------------------------------------
__global__ __launch_bounds__(256) void router_qkv_kernel(
    const float* __restrict__ x, const float* __restrict__ wrq,
    const float* __restrict__ wrk, const float* __restrict__ wrv)
{
    const int t = blockIdx.x;
    const int warp = threadIdx.x >> 5, lane = threadIdx.x & 31;
    const float* xr = x + (size_t)t * D_DIM;
    const float* aq = wrq + warp * D_DIM;
    const float* ak = wrk + warp * D_DIM;
    const float* av = wrv + warp * D_DIM;
    float sq = 0.f, sk = 0.f, sv = 0.f;
    for (int kk = lane; kk < D_DIM; kk += 32) {
        float xv = xr[kk];
        sq += xv * aq[kk]; sk += xv * ak[kk]; sv += xv * av[kk];
    }
    #pragma unroll
    for (int o = 16; o; o >>= 1) {
        sq += __shfl_down_sync(0xffffffffu, sq, o);
        sk += __shfl_down_sync(0xffffffffu, sk, o);
        sv += __shfl_down_sync(0xffffffffu, sv, o);
    }
    __shared__ float lg[3][NN];
    if (lane == 0) { lg[0][warp] = sq; lg[1][warp] = sk; lg[2][warp] = sv; }
    __syncthreads();
    if (threadIdx.x < 3) {
        float* dst = (threadIdx.x == 0) ? g_wq : (threadIdx.x == 1) ? g_wk : g_wv;
        const float* l = lg[threadIdx.x];
        float mx = l[0];
        #pragma unroll
        for (int n = 1; n < NN; n++) mx = fmaxf(mx, l[n]);
        float e[NN]; float s = 0.f;
        #pragma unroll
        for (int n = 0; n < NN; n++) { e[n] = __expf(l[n] - mx); s += e[n]; }
        float inv = 1.f / s;
        #pragma unroll
        for (int n = 0; n < NN; n++) dst[t * NN + n] = e[n] * inv;
    }
}

// ---------------- 3-term bf16 mma GEMM (unchanged, passed R4) -----------------
__global__ __launch_bounds__(256) void gemm3_kernel(
    const __nv_bfloat16* __restrict__ Ah, const __nv_bfloat16* __restrict__ Al,
    const __nv_bfloat16* __restrict__ Bh, const __nv_bfloat16* __restrict__ Bl,
    float* __restrict__ C, int M, int N, int K)
{
    extern __shared__ char sm[];
    const uint32_t sbase = smem_u32(sm);
    const int tid = threadIdx.x;
    const int lane = tid & 31, w = tid >> 5;
    const int n0 = blockIdx.x * 128, m0 = blockIdx.y * 128;
    const int wm = (w >> 2) * 64, wn = (w & 3) * 32;
    const int NC = K >> 5;

    const int ar0 = tid >> 2, ac0 = tid & 3;
    const int br0 = tid >> 4, bc0 = tid & 15;

    float acc[4][4][4];
    #pragma unroll
    for (int i = 0; i < 4; i++)
        #pragma unroll
        for (int j = 0; j < 4; j++)
            #pragma unroll
            for (int e = 0; e < 4; e++) acc[i][j][e] = 0.f;

    auto load_stage = [&](int kc, int st) {
        const uint32_t so0 = st * 32768;
        #pragma unroll
        for (int h = 0; h < 2; h++) {
            int r = ar0 + h * 64, c = ac0;
            uint32_t so = so0 + r * 64 + ((c ^ ((r >> 1) & 3)) << 4);
            size_t go = (size_t)(m0 + r) * K + kc * 32 + c * 8;
            CP16(sbase + so,        Ah + go);
            CP16(sbase + so + 8192, Al + go);
        }
        #pragma unroll
        for (int h = 0; h < 2; h++) {
            int r = br0 + h * 16, c = bc0;
            uint32_t so = so0 + 16384 + r * 256 + ((c ^ (r & 7)) << 4);
            size_t go = (size_t)(kc * 32 + r) * N + n0 + c * 8;
            CP16(sbase + so,        Bh + go);
            CP16(sbase + so + 8192, Bl + go);
        }
    };

    load_stage(0, 0);
    CP_COMMIT();

    for (int kc = 0; kc < NC; kc++) {
        const int st = kc & 1;
        if (kc + 1 < NC) {
            load_stage(kc + 1, st ^ 1);
            CP_COMMIT();
            CP_WAIT1();
        } else {
            CP_WAIT0();
        }
        __syncthreads();

        const uint32_t abase = sbase + st * 32768;
        const uint32_t bbase = abase + 16384;
        #pragma unroll
        for (int step = 0; step < 2; step++) {
            uint32_t ah[4][4], al[4][4];
            #pragma unroll
            for (int i = 0; i < 4; i++) {
                int r = wm + 16 * i + (lane & 15);
                int c = step * 2 + (lane >> 4);
                uint32_t addr = abase + r * 64 + ((c ^ ((r >> 1) & 3)) << 4);
                LDSM4(ah[i], addr);
                LDSM4(al[i], addr + 8192);
            }
            uint32_t bh[4][2], bl[4][2];
            #pragma unroll
            for (int j2 = 0; j2 < 2; j2++) {
                int r = step * 16 + (lane & 7) + ((lane >> 3) & 1) * 8;
                int c = (wn >> 3) + j2 * 2 + (lane >> 4);
                uint32_t addr = bbase + r * 256 + ((c ^ (r & 7)) << 4);
                uint32_t t[4];
                LDSM4T(t, addr);
                bh[2 * j2][0] = t[0]; bh[2 * j2][1] = t[1];
                bh[2 * j2 + 1][0] = t[2]; bh[2 * j2 + 1][1] = t[3];
                LDSM4T(t, addr + 8192);
                bl[2 * j2][0] = t[0]; bl[2 * j2][1] = t[1];
                bl[2 * j2 + 1][0] = t[2]; bl[2 * j2 + 1][1] = t[3];
            }
            #pragma unroll
            for (int i = 0; i < 4; i++)
                #pragma unroll
                for (int j = 0; j < 4; j++) {
                    MMA_BF16(acc[i][j], ah[i], bh[j]);
                    MMA_BF16(acc[i][j], al[i], bh[j]);
                    MMA_BF16(acc[i][j], ah[i], bl[j]);
                }
        }
        __syncthreads();
    }

    #pragma unroll
    for (int i = 0; i < 4; i++)
        #pragma unroll
        for (int j = 0; j < 4; j++) {
            int row = m0 + wm + 16 * i + (lane >> 2);
            int col = n0 + wn + 8 * j + ((lane & 3) << 1);
            *(float2*)&C[(size_t)row * N + col] =
                make_float2(acc[i][j][0], acc[i][j][1]);
            *(float2*)&C[(size_t)(row + 8) * N + col] =
                make_float2(acc[i][j][2], acc[i][j][3]);
        }
}

// ---------------- weighted reduce -> bf16 hi/lo q,k,v -------------------------
__global__ __launch_bounds__(256) void compress_reduce_kernel()
{
    const int idx = blockIdx.x * 256 + threadIdx.x;      // 8192*128
    const int m = idx >> 7;
    const int r4 = (idx & 127) << 2;
    const float* y = g_y + (size_t)m * (NN * R_DIM) + r4;
    const float* wq = g_wq + m * NN;
    const float* wk = g_wk + m * NN;
    const float* wv = g_wv + m * NN;
    float4 qa = {0, 0, 0, 0}, ka = {0, 0, 0, 0}, va = {0, 0, 0, 0};
    #pragma unroll
    for (int n = 0; n < NN; n++) {
        float4 t = *(const float4*)(y + n * R_DIM);
        float a = wq[n], b = wk[n], c = wv[n];
        qa.x += a * t.x; qa.y += a * t.y; qa.z += a * t.z; qa.w += a * t.w;
        ka.x += b * t.x; ka.y += b * t.y; ka.z += b * t.z; ka.w += b * t.w;
        va.x += c * t.x; va.y += c * t.y; va.z += c * t.z; va.w += c * t.w;
    }
    // q scaled by 1/8 (softmax scale / sqrt(DH))
    qa.x *= 0.125f; qa.y *= 0.125f; qa.z *= 0.125f; qa.w *= 0.125f;
    size_t o = (size_t)m * R_DIM + r4;
    float qv[4] = {qa.x, qa.y, qa.z, qa.w};
    float kv[4] = {ka.x, ka.y, ka.z, ka.w};
    float vv[4] = {va.x, va.y, va.z, va.w};
    ushort4 qh, ql, kh, kl, vh, vl;
    unsigned short *qhp = &qh.x, *qlp = &ql.x, *khp = &kh.x, *klp = &kl.x,
                   *vhp = &vh.x, *vlp = &vl.x;
    #pragma unroll
    for (int j = 0; j < 4; j++) {
        __nv_bfloat16 h;
        h = __float2bfloat16(qv[j]);
        qhp[j] = __bfloat16_as_ushort(h);
        qlp[j] = __bfloat16_as_ushort(__float2bfloat16(qv[j] - __bfloat162float(h)));
        h = __float2bfloat16(kv[j]);
        khp[j] = __bfloat16_as_ushort(h);
        klp[j] = __bfloat16_as_ushort(__float2bfloat16(kv[j] - __bfloat162float(h)));
        h = __float2bfloat16(vv[j]);
        vhp[j] = __bfloat16_as_ushort(h);
        vlp[j] = __bfloat16_as_ushort(__float2bfloat16(vv[j] - __bfloat162float(h)));
    }
    *(ushort4*)&g_qhi[o] = qh; *(ushort4*)&g_qlo[o] = ql;
    *(ushort4*)&g_khi[o] = kh; *(ushort4*)&g_klo[o] = kl;
    *(ushort4*)&g_vhi[o] = vh; *(ushort4*)&g_vlo[o] = vl;
}

__global__ __launch_bounds__(256) void expand_reduce_kernel(float* __restrict__ out)
{
    const int idx = blockIdx.x * 256 + threadIdx.x;
    const int m = idx >> 8;
    const int d4 = (idx & 255) << 2;
    const float* y = g_y + (size_t)m * (NN * D_DIM) + d4;
    const float* wo = g_wo + m * NN;
    float4 oa = {0, 0, 0, 0};
    #pragma unroll
    for (int n = 0; n < NN; n++) {
        float4 t = *(const float4*)(y + n * D_DIM);
        float a = wo[n];
        oa.x += a * t.x; oa.y += a * t.y; oa.z += a * t.z; oa.w += a * t.w;
    }
    *(float4*)&out[(size_t)m * D_DIM + d4] = oa;
}

// ---------------- mma flash attention (bf16 3-term), DH=64 --------------------
// block 128 thr (4 warps); q-tile 64 (16 rows/warp); kv-tile 64.
__global__ __launch_bounds__(128) void flash_mma_kernel()
{
    __shared__ __align__(16) char sQh[8192], sQl[8192];
    __shared__ __align__(16) char sKh[8192], sKl[8192];
    __shared__ __align__(16) char sVh[8192], sVl[8192];

    const int qt = blockIdx.x;     // 0..31
    const int bh = blockIdx.y;     // 0..31
    const int b = bh >> 3, h = bh & 7;
    const int tid = threadIdx.x, lane = tid & 31, w = tid >> 5;
    const size_t base = (size_t)b * 2048 * R_DIM + h * 64;

    const uint32_t qhS = smem_u32(sQh), qlS = smem_u32(sQl);
    const uint32_t khS = smem_u32(sKh), klS = smem_u32(sKl);
    const uint32_t vhS = smem_u32(sVh), vlS = smem_u32(sVl);

    // ---- load Q tile (rows qt*64..+63), 64 bf16/row, swizzled 128B rows ----
    {
        int r = tid >> 1;
        int gb = (tid & 1) << 2;
        size_t ro = base + (size_t)(qt * 64 + r) * R_DIM;
        #pragma unroll
        for (int i = 0; i < 4; i++) {
            int g = gb + i;
            uint32_t so = r * 128 + ((g ^ (r & 7)) << 4);
            CP16(qhS + so, g_qhi + ro + g * 8);
            CP16(qlS + so, g_qlo + ro + g * 8);
        }
        CP_COMMIT(); CP_WAIT0();
    }
    __syncthreads();

    // ---- Q A-frags (constant over kv loop) ----
    uint32_t qh[4][4], ql[4][4];
    #pragma unroll
    for (int ks = 0; ks < 4; ks++) {
        int r = (w << 4) + (lane & 15);
        int g = (ks << 1) + (lane >> 4);
        uint32_t off = r * 128 + ((g ^ (r & 7)) << 4);
        LDSM4(qh[ks], qhS + off);
        LDSM4(ql[ks], qlS + off);
    }

    float o[8][4];
    #pragma unroll
    for (int j = 0; j < 8; j++)
        #pragma unroll
        for (int e = 0; e < 4; e++) o[j][e] = 0.f;
    float m0 = -INFINITY, m1 = -INFINITY, l0 = 0.f, l1 = 0.f;

    const int row0 = (w << 4) + (lane >> 2);      // warp-local row of c0,c1

    for (int kt = 0; kt <= qt; kt++) {
        __syncthreads();   // prev tile's ldsm done
        {   // load K,V hi/lo tile (rows kt*64..+63)
            int r = tid >> 1;
            int gb = (tid & 1) << 2;
            size_t ro = base + (size_t)(kt * 64 + r) * R_DIM;
            #pragma unroll
            for (int i = 0; i < 4; i++) {
                int g = gb + i;
                uint32_t so = r * 128 + ((g ^ (r & 7)) << 4);
                CP16(khS + so, g_khi + ro + g * 8);
                CP16(klS + so, g_klo + ro + g * 8);
                CP16(vhS + so, g_vhi + ro + g * 8);
                CP16(vlS + so, g_vlo + ro + g * 8);
            }
            CP_COMMIT(); CP_WAIT0();
        }
        __syncthreads();

        // ---- S = Q K^T (64x64 per block; per warp 16x64) ----
        float s[8][4];
        #pragma unroll
        for (int j = 0; j < 8; j++)
            #pragma unroll
            for (int e = 0; e < 4; e++) s[j][e] = 0.f;

        #pragma unroll
        for (int ks = 0; ks < 4; ks++) {
            uint32_t bkh[8][2], bkl[8][2];
            #pragma unroll
            for (int jp = 0; jp < 4; jp++) {
                int rr = ((jp << 1) + ((lane >> 4) & 1)) * 8 + (lane & 7);
                int gg = (ks << 1) + ((lane >> 3) & 1);
                uint32_t off = rr * 128 + ((gg ^ (rr & 7)) << 4);
                uint32_t t[4];
                LDSM4(t, khS + off);
                bkh[2 * jp][0] = t[0]; bkh[2 * jp][1] = t[1];
                bkh[2 * jp + 1][0] = t[2]; bkh[2 * jp + 1][1] = t[3];
                LDSM4(t, klS + off);
                bkl[2 * jp][0] = t[0]; bkl[2 * jp][1] = t[1];
                bkl[2 * jp + 1][0] = t[2]; bkl[2 * jp + 1][1] = t[3];
            }
            #pragma unroll
            for (int j = 0; j < 8; j++) {
                MMA_BF16(s[j], qh[ks], bkh[j]);
                MMA_BF16(s[j], ql[ks], bkh[j]);
                MMA_BF16(s[j], qh[ks], bkl[j]);
            }
        }

        // ---- causal mask on diagonal tile ----
        if (kt == qt) {
            int colb = (lane & 3) << 1;
            #pragma unroll
            for (int j = 0; j < 8; j++) {
                int c0 = colb + (j << 3);
                if (c0     > row0)     s[j][0] = -INFINITY;
                if (c0 + 1 > row0)     s[j][1] = -INFINITY;
                if (c0     > row0 + 8) s[j][2] = -INFINITY;
                if (c0 + 1 > row0 + 8) s[j][3] = -INFINITY;
            }
        }

        // ---- online softmax (rows row0, row0+8) ----
        float mx0 = -INFINITY, mx1 = -INFINITY;
        #pragma unroll
        for (int j = 0; j < 8; j++) {
            mx0 = fmaxf(mx0, fmaxf(s[j][0], s[j][1]));
            mx1 = fmaxf(mx1, fmaxf(s[j][2], s[j][3]));
        }
        mx0 = fmaxf(mx0, __shfl_xor_sync(0xffffffffu, mx0, 1));
        mx0 = fmaxf(mx0, __shfl_xor_sync(0xffffffffu, mx0, 2));
        mx1 = fmaxf(mx1, __shfl_xor_sync(0xffffffffu, mx1, 1));
        mx1 = fmaxf(mx1, __shfl_xor_sync(0xffffffffu, mx1, 2));
        float mn0 = fmaxf(m0, mx0), mn1 = fmaxf(m1, mx1);
        float sc0 = __expf(m0 - mn0), sc1 = __expf(m1 - mn1);
        float sum0 = 0.f, sum1 = 0.f;
        #pragma unroll
        for (int j = 0; j < 8; j++) {
            s[j][0] = __expf(s[j][0] - mn0); sum0 += s[j][0];
            s[j][1] = __expf(s[j][1] - mn0); sum0 += s[j][1];
            s[j][2] = __expf(s[j][2] - mn1); sum1 += s[j][2];
            s[j][3] = __expf(s[j][3] - mn1); sum1 += s[j][3];
        }
        sum0 += __shfl_xor_sync(0xffffffffu, sum0, 1);
        sum0 += __shfl_xor_sync(0xffffffffu, sum0, 2);
        sum1 += __shfl_xor_sync(0xffffffffu, sum1, 1);
        sum1 += __shfl_xor_sync(0xffffffffu, sum1, 2);
        l0 = l0 * sc0 + sum0;  m0 = mn0;
        l1 = l1 * sc1 + sum1;  m1 = mn1;
        #pragma unroll
        for (int j = 0; j < 8; j++) {
            o[j][0] *= sc0; o[j][1] *= sc0;
            o[j][2] *= sc1; o[j][3] *= sc1;
        }

        // ---- O += P V (3-term) ----
        #pragma unroll
        for (int ks = 0; ks < 4; ks++) {
            const int j0 = ks << 1, j1 = j0 + 1;
            uint32_t pah[4], pal[4];
            PACKBF(pah[0], s[j0][0], s[j0][1]);
            PACKBF(pah[1], s[j0][2], s[j0][3]);
            PACKBF(pah[2], s[j1][0], s[j1][1]);
            PACKBF(pah[3], s[j1][2], s[j1][3]);
            PACKBF(pal[0], bflo(s[j0][0]), bflo(s[j0][1]));
            PACKBF(pal[1], bflo(s[j0][2]), bflo(s[j0][3]));
            PACKBF(pal[2], bflo(s[j1][0]), bflo(s[j1][1]));
            PACKBF(pal[3], bflo(s[j1][2]), bflo(s[j1][3]));
            uint32_t bvh[8][2], bvl[8][2];
            #pragma unroll
            for (int jp = 0; jp < 4; jp++) {
                int rr = (ks << 4) + (lane & 7) + (((lane >> 3) & 1) << 3);
                int gg = (jp << 1) + (lane >> 4);
                uint32_t off = rr * 128 + ((gg ^ (rr & 7)) << 4);
                uint32_t t[4];
                LDSM4T(t, vhS + off);
                bvh[2 * jp][0] = t[0]; bvh[2 * jp][1] = t[1];
                bvh[2 * jp + 1][0] = t[2]; bvh[2 * jp + 1][1] = t[3];
                LDSM4T(t, vlS + off);
                bvl[2 * jp][0] = t[0]; bvl[2 * jp][1] = t[1];
                bvl[2 * jp + 1][0] = t[2]; bvl[2 * jp + 1][1] = t[3];
            }
            #pragma unroll
            for (int j = 0; j < 8; j++) {
                MMA_BF16(o[j], pah, bvh[j]);
                MMA_BF16(o[j], pal, bvh[j]);
                MMA_BF16(o[j], pah, bvl[j]);
            }
        }
    }

    // ---- epilogue: normalize, write fp32 + bf16 hi/lo ----
    const float inv0 = 1.f / l0, inv1 = 1.f / l1;
    const int rg0 = qt * 64 + row0;
    #pragma unroll
    for (int j = 0; j < 8; j++) {
        int col = (j << 3) + ((lane & 3) << 1);
        size_t i0 = base + (size_t)rg0 * R_DIM + col;
        size_t i1 = i0 + 8 * R_DIM;
        float v0 = o[j][0] * inv0, v1 = o[j][1] * inv0;
        float v2 = o[j][2] * inv1, v3 = o[j][3] * inv1;
        *(float2*)&g_ao[i0] = make_float2(v0, v1);
        *(float2*)&g_ao[i1] = make_float2(v2, v3);
        uint32_t ph, pl;
        PACKBF(ph, v0, v1); PACKBF(pl, bflo(v0), bflo(v1));
        *(uint32_t*)&g_aohi[i0] = ph; *(uint32_t*)&g_aolo[i0] = pl;
        PACKBF(ph, v2, v3); PACKBF(pl, bflo(v2), bflo(v3));
        *(uint32_t*)&g_aohi[i1] = ph; *(uint32_t*)&g_aolo[i1] = pl;
    }
}

// ---------------- router softmax (expand) -------------------------------------
__global__ __launch_bounds__(256) void router_o_kernel(const float* __restrict__ wro)
{
    const int t = blockIdx.x;
    const int warp = threadIdx.x >> 5, lane = threadIdx.x & 31;
    const float* ar = g_ao + (size_t)t * R_DIM;
    const float* wn = wro + warp * R_DIM;
    float s = 0.f;
    for (int kk = lane; kk < R_DIM; kk += 32) s += ar[kk] * wn[kk];
    #pragma unroll
    for (int o = 16; o; o >>= 1) s += __shfl_down_sync(0xffffffffu, s, o);
    __shared__ float lg[NN];
    if (lane == 0) lg[warp] = s;
    __syncthreads();
    if (threadIdx.x == 0) {
        float mx = lg[0];
        #pragma unroll
        for (int n = 1; n < NN; n++) mx = fmaxf(mx, lg[n]);
        float e[NN]; float sm = 0.f;
        #pragma unroll
        for (int n = 0; n < NN; n++) { e[n] = __expf(lg[n] - mx); sm += e[n]; }
        float inv = 1.f / sm;
        #pragma unroll
        for (int n = 0; n < NN; n++) g_wo[t * NN + n] = e[n] * inv;
    }
}

// ---------------- launch ------------------------------------------------------
extern "C" void kernel_launch(void* const* d_in, const int* in_sizes, int n_in,
                              void* d_out, int out_size)
{
    const float* x   = (const float*)d_in[0];
    // d_in[1] = mask: exactly tril -> handled as causal
    const float* cn  = (const float*)d_in[2];
    const float* en  = (const float*)d_in[3];
    const float* wrq = (const float*)d_in[4];
    const float* wrk = (const float*)d_in[5];
    const float* wrv = (const float*)d_in[6];
    const float* wro = (const float*)d_in[7];
    float* out = (float*)d_out;

    static __nv_bfloat16 *p_xhi = nullptr, *p_xlo, *p_cbh, *p_cbl, *p_ebh,
                         *p_ebl, *p_aoh, *p_aol;
    static float* p_y = nullptr;
    if (!p_xhi) {
        cudaGetSymbolAddress((void**)&p_xhi, g_xhi);
        cudaGetSymbolAddress((void**)&p_xlo, g_xlo);
        cudaGetSymbolAddress((void**)&p_cbh, g_cbh);
        cudaGetSymbolAddress((void**)&p_cbl, g_cbl);
        cudaGetSymbolAddress((void**)&p_ebh, g_ebh);
        cudaGetSymbolAddress((void**)&p_ebl, g_ebl);
        cudaGetSymbolAddress((void**)&p_aoh, g_aohi);
        cudaGetSymbolAddress((void**)&p_aol, g_aolo);
        cudaGetSymbolAddress((void**)&p_y,   g_y);
        cudaFuncSetAttribute(gemm3_kernel,
                             cudaFuncAttributeMaxDynamicSharedMemorySize, 65536);
    }

    convert_x_kernel<<<1024, 256>>>(x);
    pack_cb_kernel<<<1024, 256>>>(cn);
    pack_eb_kernel<<<1024, 256>>>(en);
    router_qkv_kernel<<<T_TOK, 256>>>(x, wrq, wrk, wrv);
    // compress: Y[8192, 4096] = X[8192,1024] @ CB[1024,4096]
    gemm3_kernel<<<dim3(32, 64), 256, 65536>>>(p_xhi, p_xlo, p_cbh, p_cbl,
                                               p_y, T_TOK, NN * R_DIM, D_DIM);
    compress_reduce_kernel<<<4096, 256>>>();
    flash_mma_kernel<<<dim3(32, 32), 128>>>();
    router_o_kernel<<<T_TOK, 256>>>(wro);
    // expand: Y[8192, 8192] = AO[8192,512] @ EB[512,8192]
    gemm3_kernel<<<dim3(64, 64), 256, 65536>>>(p_aoh, p_aol, p_ebh, p_ebl,
                                               p_y, T_TOK, NN * D_DIM, R_DIM);
    expand_reduce_kernel<<<8192, 256>>>(out);
}